// round 8
// baseline (speedup 1.0000x reference)
#include <cuda_runtime.h>
#include <cuda_bf16.h>
#include <cstdint>

// out_means[b][d] = mean[d][labels[b][d]]; out_log_vars[b][d] = log_var[d][labels[b][d]]
// B = 2097152, N_DOMAINS = 8, MAX_CONCEPTS = 64.
// d_out: [means B*8 f32][log_vars B*8 f32].
//
// R8 = R6 structure (per-warp TMA bulk stores, warp-local sync, wait_group.read,
// no L2 policy) scaled to 2 samples/thread:
//  - 512 samples/CTA, 4096 CTAs (half the table-load + drain overhead)
//  - each warp owns a contiguous 64-sample slice -> one 2KB mean store +
//    one 2KB var store per warp (half the TMA command count)
//  - 4 front-batched LDG.128 label loads per thread (MLP_p1 = 4)

#define N_DOMAINS 8
#define MAX_CONCEPTS 64
#define TAB (N_DOMAINS * MAX_CONCEPTS)   // 512
#define BLK 256
#define SPW 64                           // samples per warp
#define TILE (8 * SPW)                   // 512 samples per CTA

__global__ __launch_bounds__(BLK)
void concept_gauss_kernel(const int4* __restrict__ labels4,   // [B*2]
                          const float* __restrict__ mean,     // [512]
                          const float* __restrict__ log_var,  // [512]
                          float* __restrict__ out,            // [2*B*8]
                          int B)
{
    __shared__ float s_mean[TAB];
    __shared__ float s_var[TAB];
    __shared__ alignas(128) float st_mean[TILE * N_DOMAINS];  // 16 KB, 2KB/warp
    __shared__ alignas(128) float st_var[TILE * N_DOMAINS];   // 16 KB, 2KB/warp

    const int t = threadIdx.x;
    const int w = t >> 5;
    const int lane = t & 31;

    // Cooperative table load (2 KB each), single CTA-wide barrier.
    s_mean[t]       = __ldg(&mean[t]);
    s_mean[t + 256] = __ldg(&mean[t + 256]);
    s_var[t]        = __ldg(&log_var[t]);
    s_var[t + 256]  = __ldg(&log_var[t + 256]);
    __syncthreads();

    const long base = (long)blockIdx.x * TILE;
    const bool full_tile = (base + TILE) <= (long)B;

    // Warp w owns contiguous samples [base + w*64, base + w*64 + 64).
    const long wbase = base + (long)w * SPW;
    const long b0 = wbase + lane;        // first 32 of the slice
    const long b1 = wbase + 32 + lane;   // second 32

    if (full_tile) {
        // Front-batched label loads: MLP_p1 = 4, each 128B-coalesced per warp.
        int4 a0 = __ldcs(&labels4[2 * b0]);
        int4 a1 = __ldcs(&labels4[2 * b0 + 1]);
        int4 c0 = __ldcs(&labels4[2 * b1]);
        int4 c1 = __ldcs(&labels4[2 * b1 + 1]);

        const int s0 = w * SPW + lane;        // staging slot, sample 0
        const int s1 = w * SPW + 32 + lane;   // staging slot, sample 1

        float4* pm0 = reinterpret_cast<float4*>(&st_mean[s0 * N_DOMAINS]);
        float4* pm1 = reinterpret_cast<float4*>(&st_mean[s1 * N_DOMAINS]);
        float4* pv0 = reinterpret_cast<float4*>(&st_var[s0 * N_DOMAINS]);
        float4* pv1 = reinterpret_cast<float4*>(&st_var[s1 * N_DOMAINS]);

        pm0[0] = make_float4(s_mean[0 * MAX_CONCEPTS + a0.x],
                             s_mean[1 * MAX_CONCEPTS + a0.y],
                             s_mean[2 * MAX_CONCEPTS + a0.z],
                             s_mean[3 * MAX_CONCEPTS + a0.w]);
        pm0[1] = make_float4(s_mean[4 * MAX_CONCEPTS + a1.x],
                             s_mean[5 * MAX_CONCEPTS + a1.y],
                             s_mean[6 * MAX_CONCEPTS + a1.z],
                             s_mean[7 * MAX_CONCEPTS + a1.w]);
        pm1[0] = make_float4(s_mean[0 * MAX_CONCEPTS + c0.x],
                             s_mean[1 * MAX_CONCEPTS + c0.y],
                             s_mean[2 * MAX_CONCEPTS + c0.z],
                             s_mean[3 * MAX_CONCEPTS + c0.w]);
        pm1[1] = make_float4(s_mean[4 * MAX_CONCEPTS + c1.x],
                             s_mean[5 * MAX_CONCEPTS + c1.y],
                             s_mean[6 * MAX_CONCEPTS + c1.z],
                             s_mean[7 * MAX_CONCEPTS + c1.w]);

        pv0[0] = make_float4(s_var[0 * MAX_CONCEPTS + a0.x],
                             s_var[1 * MAX_CONCEPTS + a0.y],
                             s_var[2 * MAX_CONCEPTS + a0.z],
                             s_var[3 * MAX_CONCEPTS + a0.w]);
        pv0[1] = make_float4(s_var[4 * MAX_CONCEPTS + a1.x],
                             s_var[5 * MAX_CONCEPTS + a1.y],
                             s_var[6 * MAX_CONCEPTS + a1.z],
                             s_var[7 * MAX_CONCEPTS + a1.w]);
        pv1[0] = make_float4(s_var[0 * MAX_CONCEPTS + c0.x],
                             s_var[1 * MAX_CONCEPTS + c0.y],
                             s_var[2 * MAX_CONCEPTS + c0.z],
                             s_var[3 * MAX_CONCEPTS + c0.w]);
        pv1[1] = make_float4(s_var[4 * MAX_CONCEPTS + c1.x],
                             s_var[5 * MAX_CONCEPTS + c1.y],
                             s_var[6 * MAX_CONCEPTS + c1.z],
                             s_var[7 * MAX_CONCEPTS + c1.w]);

        // Warp-local completion of this warp's 2KB staging slices.
        __syncwarp();

        if (lane == 0) {
            // Order this warp's generic-proxy STS before async-proxy TMA reads.
            asm volatile("fence.proxy.async.shared::cta;" ::: "memory");

            uint32_t sm_m, sm_v;
            asm("{ .reg .u64 a; cvta.to.shared.u64 a, %1; cvt.u32.u64 %0, a; }"
                : "=r"(sm_m) : "l"(&st_mean[w * SPW * N_DOMAINS]));
            asm("{ .reg .u64 a; cvta.to.shared.u64 a, %1; cvt.u32.u64 %0, a; }"
                : "=r"(sm_v) : "l"(&st_var[w * SPW * N_DOMAINS]));

            const uint32_t bytes = SPW * N_DOMAINS * sizeof(float);  // 2048
            float* dst_m = out + wbase * N_DOMAINS;
            float* dst_v = out + (long)B * N_DOMAINS + wbase * N_DOMAINS;

            asm volatile(
                "cp.async.bulk.global.shared::cta.bulk_group [%0], [%1], %2;"
                :: "l"(dst_m), "r"(sm_m), "r"(bytes) : "memory");
            asm volatile(
                "cp.async.bulk.global.shared::cta.bulk_group [%0], [%1], %2;"
                :: "l"(dst_v), "r"(sm_v), "r"(bytes) : "memory");
            asm volatile("cp.async.bulk.commit_group;" ::: "memory");
            // Wait only for TMA smem READ completion; lane 0's residency keeps
            // the CTA's smem alive, other lanes exit immediately.
            asm volatile("cp.async.bulk.wait_group.read 0;" ::: "memory");
        }
    } else {
        // Tail (unused for B = 2^21): direct stores.
        long vb = 2L * B;  // float4 units
        float4* o = reinterpret_cast<float4*>(out);
        long bs[2] = {b0, b1};
        for (int s = 0; s < 2; s++) {
            long b = bs[s];
            if (b >= B) continue;
            int4 l0 = __ldcs(&labels4[2 * b]);
            int4 l1 = __ldcs(&labels4[2 * b + 1]);
            o[2 * b]     = make_float4(s_mean[0 * MAX_CONCEPTS + l0.x],
                                       s_mean[1 * MAX_CONCEPTS + l0.y],
                                       s_mean[2 * MAX_CONCEPTS + l0.z],
                                       s_mean[3 * MAX_CONCEPTS + l0.w]);
            o[2 * b + 1] = make_float4(s_mean[4 * MAX_CONCEPTS + l1.x],
                                       s_mean[5 * MAX_CONCEPTS + l1.y],
                                       s_mean[6 * MAX_CONCEPTS + l1.z],
                                       s_mean[7 * MAX_CONCEPTS + l1.w]);
            o[vb + 2 * b]     = make_float4(s_var[0 * MAX_CONCEPTS + l0.x],
                                            s_var[1 * MAX_CONCEPTS + l0.y],
                                            s_var[2 * MAX_CONCEPTS + l0.z],
                                            s_var[3 * MAX_CONCEPTS + l0.w]);
            o[vb + 2 * b + 1] = make_float4(s_var[4 * MAX_CONCEPTS + l1.x],
                                            s_var[5 * MAX_CONCEPTS + l1.y],
                                            s_var[6 * MAX_CONCEPTS + l1.z],
                                            s_var[7 * MAX_CONCEPTS + l1.w]);
        }
    }
}

extern "C" void kernel_launch(void* const* d_in, const int* in_sizes, int n_in,
                              void* d_out, int out_size) {
    const int4*  labels4 = (const int4*)d_in[0];
    const float* mean    = (const float*)d_in[1];
    const float* log_var = (const float*)d_in[2];
    float* out = (float*)d_out;

    int B = in_sizes[0] / N_DOMAINS;     // 2097152
    int blocks = (B + TILE - 1) / TILE;  // 4096
    concept_gauss_kernel<<<blocks, BLK>>>(labels4, mean, log_var, out, B);
}

// round 9
// speedup vs baseline: 1.0580x; 1.0580x over previous
#include <cuda_runtime.h>
#include <cuda_bf16.h>
#include <cstdint>

// out_means[b][d] = mean[d][labels[b][d]]; out_log_vars[b][d] = log_var[d][labels[b][d]]
// B = 2097152, N_DOMAINS = 8, MAX_CONCEPTS = 64.
// d_out: [means B*8 f32][log_vars B*8 f32].
//
// R9 = R6 (best wall: 256 samples/CTA, per-warp 1KB TMA bulk stores, warp-local
// sync, wait_group.read, lane-0-only drain) + label LDGs HOISTED above the
// table-load barrier. The label loads depend on nothing; ptxas won't hoist
// LDGs across BAR.SYNC itself, so doing it in source overlaps their ~600cyc
// DRAM latency with the table load + barrier, shortening every CTA's critical
// path.

#define N_DOMAINS 8
#define MAX_CONCEPTS 64
#define TAB (N_DOMAINS * MAX_CONCEPTS)   // 512
#define BLK 256

__global__ __launch_bounds__(BLK)
void concept_gauss_kernel(const int4* __restrict__ labels4,   // [B*2]
                          const float* __restrict__ mean,     // [512]
                          const float* __restrict__ log_var,  // [512]
                          float* __restrict__ out,            // [2*B*8]
                          int B)
{
    __shared__ float s_mean[TAB];
    __shared__ float s_var[TAB];
    __shared__ alignas(128) float st_mean[BLK * N_DOMAINS];  // 8 KB, 1KB/warp
    __shared__ alignas(128) float st_var[BLK * N_DOMAINS];   // 8 KB, 1KB/warp

    const int t = threadIdx.x;
    const int w = t >> 5;
    const int lane = t & 31;

    const long base = (long)blockIdx.x * BLK;
    const long b    = base + t;
    const bool full_block = (base + BLK) <= (long)B;
    const bool live = b < (long)B;

    // ---- FIRST: issue the label loads (no dependencies) so their DRAM
    // latency overlaps the table load + barrier below.
    int4 l0 = make_int4(0, 0, 0, 0), l1 = make_int4(0, 0, 0, 0);
    if (live) {
        l0 = __ldcs(&labels4[2 * b]);
        l1 = __ldcs(&labels4[2 * b + 1]);
    }

    // ---- Table load (2 KB each) + the only CTA-wide barrier.
    s_mean[t]       = __ldg(&mean[t]);
    s_mean[t + 256] = __ldg(&mean[t + 256]);
    s_var[t]        = __ldg(&log_var[t]);
    s_var[t + 256]  = __ldg(&log_var[t + 256]);
    __syncthreads();

    if (full_block) {
        float4* pm = reinterpret_cast<float4*>(&st_mean[t * N_DOMAINS]);
        float4* pv = reinterpret_cast<float4*>(&st_var[t * N_DOMAINS]);

        pm[0] = make_float4(s_mean[0 * MAX_CONCEPTS + l0.x],
                            s_mean[1 * MAX_CONCEPTS + l0.y],
                            s_mean[2 * MAX_CONCEPTS + l0.z],
                            s_mean[3 * MAX_CONCEPTS + l0.w]);
        pm[1] = make_float4(s_mean[4 * MAX_CONCEPTS + l1.x],
                            s_mean[5 * MAX_CONCEPTS + l1.y],
                            s_mean[6 * MAX_CONCEPTS + l1.z],
                            s_mean[7 * MAX_CONCEPTS + l1.w]);
        pv[0] = make_float4(s_var[0 * MAX_CONCEPTS + l0.x],
                            s_var[1 * MAX_CONCEPTS + l0.y],
                            s_var[2 * MAX_CONCEPTS + l0.z],
                            s_var[3 * MAX_CONCEPTS + l0.w]);
        pv[1] = make_float4(s_var[4 * MAX_CONCEPTS + l1.x],
                            s_var[5 * MAX_CONCEPTS + l1.y],
                            s_var[6 * MAX_CONCEPTS + l1.z],
                            s_var[7 * MAX_CONCEPTS + l1.w]);

        // Warp-local completion of this warp's 1KB staging slices.
        __syncwarp();

        if (lane == 0) {
            // Order this warp's generic-proxy STS before async-proxy TMA reads.
            asm volatile("fence.proxy.async.shared::cta;" ::: "memory");

            uint32_t sm_m, sm_v;
            asm("{ .reg .u64 a; cvta.to.shared.u64 a, %1; cvt.u32.u64 %0, a; }"
                : "=r"(sm_m) : "l"(&st_mean[w * 32 * N_DOMAINS]));
            asm("{ .reg .u64 a; cvta.to.shared.u64 a, %1; cvt.u32.u64 %0, a; }"
                : "=r"(sm_v) : "l"(&st_var[w * 32 * N_DOMAINS]));

            const uint32_t bytes = 32 * N_DOMAINS * sizeof(float);  // 1024
            float* dst_m = out + (base + w * 32) * N_DOMAINS;
            float* dst_v = out + (long)B * N_DOMAINS + (base + w * 32) * N_DOMAINS;

            asm volatile(
                "cp.async.bulk.global.shared::cta.bulk_group [%0], [%1], %2;"
                :: "l"(dst_m), "r"(sm_m), "r"(bytes) : "memory");
            asm volatile(
                "cp.async.bulk.global.shared::cta.bulk_group [%0], [%1], %2;"
                :: "l"(dst_v), "r"(sm_v), "r"(bytes) : "memory");
            asm volatile("cp.async.bulk.commit_group;" ::: "memory");
            // Wait only for TMA smem READ completion; lane 0's residency keeps
            // the CTA's smem alive, other lanes exit immediately.
            asm volatile("cp.async.bulk.wait_group.read 0;" ::: "memory");
        }
    } else {
        // Tail (unused for B = 2^21): direct stores.
        if (live) {
            float4* o = reinterpret_cast<float4*>(out);
            long vb = 2L * B;  // float4 units
            o[2 * b]     = make_float4(s_mean[0 * MAX_CONCEPTS + l0.x],
                                       s_mean[1 * MAX_CONCEPTS + l0.y],
                                       s_mean[2 * MAX_CONCEPTS + l0.z],
                                       s_mean[3 * MAX_CONCEPTS + l0.w]);
            o[2 * b + 1] = make_float4(s_mean[4 * MAX_CONCEPTS + l1.x],
                                       s_mean[5 * MAX_CONCEPTS + l1.y],
                                       s_mean[6 * MAX_CONCEPTS + l1.z],
                                       s_mean[7 * MAX_CONCEPTS + l1.w]);
            o[vb + 2 * b]     = make_float4(s_var[0 * MAX_CONCEPTS + l0.x],
                                            s_var[1 * MAX_CONCEPTS + l0.y],
                                            s_var[2 * MAX_CONCEPTS + l0.z],
                                            s_var[3 * MAX_CONCEPTS + l0.w]);
            o[vb + 2 * b + 1] = make_float4(s_var[4 * MAX_CONCEPTS + l1.x],
                                            s_var[5 * MAX_CONCEPTS + l1.y],
                                            s_var[6 * MAX_CONCEPTS + l1.z],
                                            s_var[7 * MAX_CONCEPTS + l1.w]);
        }
    }
}

extern "C" void kernel_launch(void* const* d_in, const int* in_sizes, int n_in,
                              void* d_out, int out_size) {
    const int4*  labels4 = (const int4*)d_in[0];
    const float* mean    = (const float*)d_in[1];
    const float* log_var = (const float*)d_in[2];
    float* out = (float*)d_out;

    int B = in_sizes[0] / N_DOMAINS;   // 2097152
    int blocks = (B + BLK - 1) / BLK;  // 8192
    concept_gauss_kernel<<<blocks, BLK>>>(labels4, mean, log_var, out, B);
}